// round 10
// baseline (speedup 1.0000x reference)
#include <cuda_runtime.h>
#include <cuda_bf16.h>
#include <cstddef>

// ---------------- problem constants ----------------
#define B_     256
#define T_     200
#define KDEP   5
#define EMB_   300
#define SMALLD 30
#define IN_DIM 360      // 300 + 30 + 30
#define IN0    390      // 360 + 30 (true K of GEMM0)
#define MEM_   300
#define BT_    (B_*T_)  // 51200
#define SLD    400      // S1 row stride (390 valid, pads zero) = GEMM0 padded K
#define HLD    304      // h / S2 row stride (300 valid, pads zero) = GEMM1 padded K

// ---------------- static device scratch (zero-initialized, never freed) ----------------
__device__ __align__(16) float g_x[(size_t)BT_*IN_DIM + 64]; // x [BT,360]; reused as S2 [BT,304]
__device__ __align__(16) float g_S[(size_t)BT_*SLD   + 64];  // S1 [BT,400]; cols 390..399 stay 0
__device__ __align__(16) float g_h[(size_t)BT_*HLD   + 64];  // h  [BT,304]; cols 300..303 stay 0
__device__ float g_invden[BT_];
__device__ float g_maskpad[BT_];

// ---------------- prep: embedding gathers + dep ragged sum ----------------
__global__ void prep_kernel(const int* __restrict__ words, const int* __restrict__ pos,
                            const int* __restrict__ ner, const int* __restrict__ dep_ids,
                            const int* __restrict__ dep_mask,
                            const float* __restrict__ word_emb, const float* __restrict__ pos_emb,
                            const float* __restrict__ ner_emb, const float* __restrict__ dep_emb)
{
    int warp = threadIdx.x >> 5, lane = threadIdx.x & 31;
    int i = blockIdx.x * 8 + warp;            // token index
    if (i >= BT_) return;

    const float* wrow = word_emb + (size_t)words[i] * EMB_;
    float* xrow = g_x + (size_t)i * IN_DIM;
    #pragma unroll
    for (int j = lane; j < EMB_; j += 32) xrow[j] = wrow[j];

    if (lane < SMALLD) {
        xrow[300 + lane] = pos_emb[pos[i] * SMALLD + lane];
        xrow[330 + lane] = ner_emb[ner[i] * SMALLD + lane];
        float s = 0.f; int cnt = 0;
        #pragma unroll
        for (int k = 0; k < KDEP; k++) {
            int m = dep_mask[i * KDEP + k];
            cnt += m;
            if (m) s += dep_emb[dep_ids[i * KDEP + k] * SMALLD + lane];
        }
        if (cnt == 0) s = dep_emb[lane];          // dep_emb[0]
        s += dep_emb[SMALLD + lane];              // + dep_emb[SELF_LOOP_ID=1]
        g_S[(size_t)i * SLD + IN_DIM + lane] = s; // cols 360..389
    }
}

// ---------------- denom (1/(rowsum+1)) + out_mask ----------------
__global__ void maskden_kernel(const int* __restrict__ adj, float* __restrict__ mask_out)
{
    __shared__ float rs_sh[T_];
    int b = blockIdx.x;
    int tid = threadIdx.x;                     // 256
    const int* Ab = adj + (size_t)b * T_ * T_;

    int col = 0;
    if (tid < T_) {
        for (int s = 0; s < T_; s++) col += Ab[s * T_ + tid];
    }
    int warp = tid >> 5, lane = tid & 31;
    for (int row = warp; row < T_; row += 8) {
        int acc = 0;
        for (int j = lane; j < T_; j += 32) acc += Ab[row * T_ + j];
        #pragma unroll
        for (int off = 16; off; off >>= 1) acc += __shfl_down_sync(0xffffffffu, acc, off);
        if (lane == 0) rs_sh[row] = (float)acc;
    }
    __syncthreads();
    if (tid < T_) {
        float rs = rs_sh[tid];
        g_invden[b * T_ + tid] = 1.0f / (rs + 1.0f);
        mask_out[b * T_ + tid] = ((rs + (float)col) == 0.0f) ? 1.0f : 0.0f;
    }
}

// ---------------- batched einsum: Out[b] = adj[b] @ X[b] + X[b] ----------------
// 64x64 tile, BK=8 (200 = 25*8, no K guards), 256 threads, 4x4/thread, double-buffered.
// Columns [Ncols, padz) of Out are written 0 (to establish zero K-padding for the
// following dense GEMM); columns >= padz untouched.
__global__ void __launch_bounds__(256) einsum_kernel(const int* __restrict__ adj,
                              const float* __restrict__ X, int ldx,
                              float* __restrict__ Out, int ldo, int Ncols, int padz)
{
    __shared__ __align__(16) float As[2][8][68];   // [k][m], padded
    __shared__ __align__(16) float Bs[2][8][68];   // [k][n], padded
    const int b  = blockIdx.z;
    const int m0 = blockIdx.y * 64;
    const int n0 = blockIdx.x * 64;
    const int tid = threadIdx.x;
    const int tr = tid >> 4, tc = tid & 15;
    const int* Ab = adj + (size_t)b * (T_ * T_);
    const float* Xb = X + (size_t)b * T_ * ldx;

    float ra[2], rb[2];
    // ---- prologue: load k0 = 0 into buffer 0 ----
    #pragma unroll
    for (int i = 0; i < 2; i++) {
        int slot = tid + i * 256;                // 64m x 8k
        int r = slot >> 3, c = slot & 7;
        ra[i] = (m0 + r < T_) ? (float)Ab[(m0 + r) * T_ + c] : 0.f;
    }
    #pragma unroll
    for (int i = 0; i < 2; i++) {
        int idx = tid + i * 256;                 // 8k x 64n
        int r = idx >> 6, c = idx & 63;
        rb[i] = (n0 + c < Ncols) ? Xb[r * ldx + n0 + c] : 0.f;
    }
    #pragma unroll
    for (int i = 0; i < 2; i++) { int s = tid + i*256; As[0][s & 7][s >> 3] = ra[i]; }
    #pragma unroll
    for (int i = 0; i < 2; i++) { int s = tid + i*256; Bs[0][s >> 6][s & 63] = rb[i]; }
    __syncthreads();

    float acc[4][4] = {};
    const int NSTEP = T_ / 8;                    // 25
    for (int s = 0; s < NSTEP; s++) {
        int p = s & 1;
        if (s + 1 < NSTEP) {
            int k0 = (s + 1) * 8;
            #pragma unroll
            for (int i = 0; i < 2; i++) {
                int slot = tid + i * 256;
                int r = slot >> 3, c = slot & 7;
                ra[i] = (m0 + r < T_) ? (float)Ab[(m0 + r) * T_ + k0 + c] : 0.f;
            }
            #pragma unroll
            for (int i = 0; i < 2; i++) {
                int idx = tid + i * 256;
                int r = idx >> 6, c = idx & 63;
                rb[i] = (n0 + c < Ncols) ? Xb[(k0 + r) * ldx + n0 + c] : 0.f;
            }
        }
        #pragma unroll
        for (int kk = 0; kk < 8; kk++) {
            float4 a  = *reinterpret_cast<const float4*>(&As[p][kk][tr * 4]);
            float4 bv = *reinterpret_cast<const float4*>(&Bs[p][kk][tc * 4]);
            float av[4] = {a.x, a.y, a.z, a.w};
            float bw[4] = {bv.x, bv.y, bv.z, bv.w};
            #pragma unroll
            for (int i = 0; i < 4; i++)
                #pragma unroll
                for (int j = 0; j < 4; j++)
                    acc[i][j] = fmaf(av[i], bw[j], acc[i][j]);
        }
        if (s + 1 < NSTEP) {
            int q = 1 - p;
            #pragma unroll
            for (int i = 0; i < 2; i++) { int t = tid + i*256; As[q][t & 7][t >> 3] = ra[i]; }
            #pragma unroll
            for (int i = 0; i < 2; i++) { int t = tid + i*256; Bs[q][t >> 6][t & 63] = rb[i]; }
            __syncthreads();
        }
    }
    #pragma unroll
    for (int i = 0; i < 4; i++) {
        int m = m0 + tr * 4 + i;
        if (m >= T_) continue;
        #pragma unroll
        for (int j = 0; j < 4; j++) {
            int n = n0 + tc * 4 + j;
            float* o = &Out[((size_t)b * T_ + m) * ldo + n];
            if (n < Ncols)       *o = acc[i][j] + Xb[m * ldx + n];
            else if (n < padz)   *o = 0.f;
        }
    }
}

// ---------------- dense GEMM: C = relu((A@W + 2*bias) * invden) ----------------
// 256x64 tile, BK=16, 256 threads, 8x8/thread, double-buffered.
// M % 256 == 0. A is read guard-free as float4 over [0, 16*nsteps) columns of each
// row (lda >= 16*nsteps, pad columns are zero). W guarded with true K, N.
__global__ void __launch_bounds__(256) dense_gemm_kernel(
        const float* __restrict__ A, int lda, int nsteps,
        const float* __restrict__ W, int K, int N,
        const float* __restrict__ bias, const float* __restrict__ invden,
        float* __restrict__ C, int ldc)
{
    __shared__ __align__(16) float As[2][16][260];   // [k][m], padded
    __shared__ __align__(16) float Bs[2][16][68];    // [k][n], padded
    const int tid = threadIdx.x;
    const int m0 = blockIdx.y * 256;
    const int n0 = blockIdx.x * 64;
    const int tr = tid >> 3, tc = tid & 7;           // 32 x 8 thread grid

    float4 ra[4]; float rb[4];
    // ---- prologue: k0 = 0 into buffer 0 ----
    #pragma unroll
    for (int i = 0; i < 4; i++) {
        int slot = tid + i * 256;                    // 1024 float4 slots = 256m x 16k
        int r = slot >> 2, cq = slot & 3;
        ra[i] = *reinterpret_cast<const float4*>(&A[(size_t)(m0 + r) * lda + cq * 4]);
    }
    #pragma unroll
    for (int i = 0; i < 4; i++) {
        int idx = tid + i * 256;                     // 16k x 64n
        int r = idx >> 6, c = idx & 63;
        rb[i] = (r < K && n0 + c < N) ? W[(size_t)r * N + n0 + c] : 0.f;
    }
    #pragma unroll
    for (int i = 0; i < 4; i++) {
        int slot = tid + i * 256; int r = slot >> 2, cq = slot & 3;
        As[0][cq*4+0][r] = ra[i].x; As[0][cq*4+1][r] = ra[i].y;
        As[0][cq*4+2][r] = ra[i].z; As[0][cq*4+3][r] = ra[i].w;
    }
    #pragma unroll
    for (int i = 0; i < 4; i++) { int t = tid + i*256; Bs[0][t >> 6][t & 63] = rb[i]; }
    __syncthreads();

    float acc[8][8] = {};
    for (int s = 0; s < nsteps; s++) {
        int p = s & 1;
        if (s + 1 < nsteps) {
            int k0 = (s + 1) * 16;
            #pragma unroll
            for (int i = 0; i < 4; i++) {
                int slot = tid + i * 256; int r = slot >> 2, cq = slot & 3;
                ra[i] = *reinterpret_cast<const float4*>(&A[(size_t)(m0 + r) * lda + k0 + cq * 4]);
            }
            #pragma unroll
            for (int i = 0; i < 4; i++) {
                int idx = tid + i * 256; int r = idx >> 6, c = idx & 63;
                int gk = k0 + r;
                rb[i] = (gk < K && n0 + c < N) ? W[(size_t)gk * N + n0 + c] : 0.f;
            }
        }
        #pragma unroll
        for (int kk = 0; kk < 16; kk++) {
            float4 a0 = *reinterpret_cast<const float4*>(&As[p][kk][tr * 8]);
            float4 a1 = *reinterpret_cast<const float4*>(&As[p][kk][tr * 8 + 4]);
            float4 b0 = *reinterpret_cast<const float4*>(&Bs[p][kk][tc * 8]);
            float4 b1 = *reinterpret_cast<const float4*>(&Bs[p][kk][tc * 8 + 4]);
            float av[8] = {a0.x,a0.y,a0.z,a0.w,a1.x,a1.y,a1.z,a1.w};
            float bv[8] = {b0.x,b0.y,b0.z,b0.w,b1.x,b1.y,b1.z,b1.w};
            #pragma unroll
            for (int i = 0; i < 8; i++)
                #pragma unroll
                for (int j = 0; j < 8; j++)
                    acc[i][j] = fmaf(av[i], bv[j], acc[i][j]);
        }
        if (s + 1 < nsteps) {
            int q = 1 - p;
            #pragma unroll
            for (int i = 0; i < 4; i++) {
                int slot = tid + i * 256; int r = slot >> 2, cq = slot & 3;
                As[q][cq*4+0][r] = ra[i].x; As[q][cq*4+1][r] = ra[i].y;
                As[q][cq*4+2][r] = ra[i].z; As[q][cq*4+3][r] = ra[i].w;
            }
            #pragma unroll
            for (int i = 0; i < 4; i++) { int t = tid + i*256; Bs[q][t >> 6][t & 63] = rb[i]; }
            __syncthreads();
        }
    }

    // ---- epilogue: relu((acc + 2b) * invden) ----
    float bn[8];
    #pragma unroll
    for (int j = 0; j < 8; j++) {
        int n = n0 + tc * 8 + j;
        bn[j] = (n < N) ? 2.0f * bias[n] : 0.f;
    }
    const bool full = (n0 + 64 <= N);
    #pragma unroll
    for (int i = 0; i < 8; i++) {
        int m = m0 + tr * 8 + i;
        float inv = invden[m];
        float v[8];
        #pragma unroll
        for (int j = 0; j < 8; j++) v[j] = fmaxf((acc[i][j] + bn[j]) * inv, 0.f);
        float* cp = &C[(size_t)m * ldc + n0 + tc * 8];
        if (full) {
            *reinterpret_cast<float4*>(cp)     = make_float4(v[0], v[1], v[2], v[3]);
            *reinterpret_cast<float4*>(cp + 4) = make_float4(v[4], v[5], v[6], v[7]);
        } else {
            #pragma unroll
            for (int j = 0; j < 8; j++)
                if (n0 + tc * 8 + j < N) cp[j] = v[j];
        }
    }
}

// ---------------- launch ----------------
extern "C" void kernel_launch(void* const* d_in, const int* in_sizes, int n_in,
                              void* d_out, int out_size)
{
    const int* adj      = (const int*)d_in[0];
    const int* words    = (const int*)d_in[1];
    const int* pos      = (const int*)d_in[2];
    const int* ner      = (const int*)d_in[3];
    const int* dep_ids  = (const int*)d_in[4];
    const int* dep_mask = (const int*)d_in[5];
    int base = n_in - 8;                    // trailing 8 arrays are fixed
    const float* word_emb = (const float*)d_in[base + 0];
    const float* pos_emb  = (const float*)d_in[base + 1];
    const float* ner_emb  = (const float*)d_in[base + 2];
    const float* dep_emb  = (const float*)d_in[base + 3];
    const float* W0_w     = (const float*)d_in[base + 4];
    const float* W0_b     = (const float*)d_in[base + 5];
    const float* W1_w     = (const float*)d_in[base + 6];
    const float* W1_b     = (const float*)d_in[base + 7];

    float* out = (float*)d_out;

    void *px, *pS, *ph, *pinv, *pmaskpad;
    cudaGetSymbolAddress(&px, g_x);
    cudaGetSymbolAddress(&pS, g_S);
    cudaGetSymbolAddress(&ph, g_h);
    cudaGetSymbolAddress(&pinv, g_invden);
    cudaGetSymbolAddress(&pmaskpad, g_maskpad);
    float* gx   = (float*)px;
    float* gS   = (float*)pS;
    float* gh   = (float*)ph;
    float* ginv = (float*)pinv;

    float* mask_out = ((long long)out_size >= (long long)BT_ * MEM_ + BT_)
                        ? (out + (size_t)BT_ * MEM_) : (float*)pmaskpad;

    dim3 blk(256);

    // 1) embeddings + dep columns of S1
    prep_kernel<<<BT_ / 8, blk>>>(words, pos, ner, dep_ids, dep_mask,
                                  word_emb, pos_emb, ner_emb, dep_emb);

    // 2) denom + out_mask
    maskden_kernel<<<B_, blk>>>(adj, mask_out);

    // 3) S1[:, :360] = A@x + x            (cols 360..389 = dep from prep; 390..399 zero)
    einsum_kernel<<<dim3(6, 4, B_), blk>>>(adj, gx, IN_DIM, gS, SLD, IN_DIM, IN_DIM);

    // 4) h = relu((S1 @ W0 + 2*b0) * invden)   K=390 padded to 400 (25 steps)
    dense_gemm_kernel<<<dim3(5, BT_ / 256), blk>>>(gS, SLD, 25, W0_w, IN0, MEM_,
                                                   W0_b, ginv, gh, HLD);

    // 5) S2 = A@h + h  (into g_x, stride 304; cols 300..303 zero-filled)
    einsum_kernel<<<dim3(5, 4, B_), blk>>>(adj, gh, HLD, gx, HLD, MEM_, HLD);

    // 6) out = relu((S2 @ W1 + 2*b1) * invden)  K=300 padded to 304 (19 steps)
    dense_gemm_kernel<<<dim3(5, BT_ / 256), blk>>>(gx, HLD, 19, W1_w, MEM_, MEM_,
                                                   W1_b, ginv, out, MEM_);
}

// round 11
// speedup vs baseline: 1.0065x; 1.0065x over previous
#include <cuda_runtime.h>
#include <cuda_bf16.h>
#include <cstddef>

// ---------------- problem constants ----------------
#define B_     256
#define T_     200
#define KDEP   5
#define EMB_   300
#define SMALLD 30
#define IN_DIM 360      // 300 + 30 + 30
#define IN0    390      // 360 + 30 (true K of GEMM0)
#define MEM_   300
#define BT_    (B_*T_)  // 51200
#define SLD    400      // S1 row stride (390 valid, pads zero) = GEMM0 padded K
#define HLD    304      // h / S2 row stride (300 valid, pads zero) = GEMM1 padded K

// ---------------- static device scratch (zero-initialized, never freed) ----------------
__device__ __align__(16) float g_x[(size_t)BT_*IN_DIM + 64]; // x [BT,360]; reused as S2 [BT,304]
__device__ __align__(16) float g_S[(size_t)BT_*SLD   + 64];  // S1 [BT,400]; cols 390..399 stay 0
__device__ __align__(16) float g_h[(size_t)BT_*HLD   + 64];  // h  [BT,304]; cols 300..303 stay 0
__device__ float g_invden[BT_];
__device__ float g_maskpad[BT_];

// ---------------- prep: embedding gathers + dep ragged sum ----------------
__global__ void prep_kernel(const int* __restrict__ words, const int* __restrict__ pos,
                            const int* __restrict__ ner, const int* __restrict__ dep_ids,
                            const int* __restrict__ dep_mask,
                            const float* __restrict__ word_emb, const float* __restrict__ pos_emb,
                            const float* __restrict__ ner_emb, const float* __restrict__ dep_emb)
{
    int warp = threadIdx.x >> 5, lane = threadIdx.x & 31;
    int i = blockIdx.x * 8 + warp;            // token index
    if (i >= BT_) return;

    const float* wrow = word_emb + (size_t)words[i] * EMB_;
    float* xrow = g_x + (size_t)i * IN_DIM;
    #pragma unroll
    for (int j = lane; j < EMB_; j += 32) xrow[j] = wrow[j];

    if (lane < SMALLD) {
        xrow[300 + lane] = pos_emb[pos[i] * SMALLD + lane];
        xrow[330 + lane] = ner_emb[ner[i] * SMALLD + lane];
        float s = 0.f; int cnt = 0;
        #pragma unroll
        for (int k = 0; k < KDEP; k++) {
            int m = dep_mask[i * KDEP + k];
            cnt += m;
            if (m) s += dep_emb[dep_ids[i * KDEP + k] * SMALLD + lane];
        }
        if (cnt == 0) s = dep_emb[lane];          // dep_emb[0]
        s += dep_emb[SMALLD + lane];              // + dep_emb[SELF_LOOP_ID=1]
        g_S[(size_t)i * SLD + IN_DIM + lane] = s; // cols 360..389
    }
}

// ---------------- denom (1/(rowsum+1)) + out_mask ----------------
__global__ void maskden_kernel(const int* __restrict__ adj, float* __restrict__ mask_out)
{
    __shared__ float rs_sh[T_];
    int b = blockIdx.x;
    int tid = threadIdx.x;                     // 256
    const int* Ab = adj + (size_t)b * T_ * T_;

    int col = 0;
    if (tid < T_) {
        for (int s = 0; s < T_; s++) col += Ab[s * T_ + tid];
    }
    int warp = tid >> 5, lane = tid & 31;
    for (int row = warp; row < T_; row += 8) {
        int acc = 0;
        for (int j = lane; j < T_; j += 32) acc += Ab[row * T_ + j];
        #pragma unroll
        for (int off = 16; off; off >>= 1) acc += __shfl_down_sync(0xffffffffu, acc, off);
        if (lane == 0) rs_sh[row] = (float)acc;
    }
    __syncthreads();
    if (tid < T_) {
        float rs = rs_sh[tid];
        g_invden[b * T_ + tid] = 1.0f / (rs + 1.0f);
        mask_out[b * T_ + tid] = ((rs + (float)col) == 0.0f) ? 1.0f : 0.0f;
    }
}

// ---------------- batched einsum: Out[b] = adj[b] @ X[b] + X[b] ----------------
// 64x64 tile, BK=8 (200 = 25*8, no K guards), 256 threads, 4x4/thread, double-buffered.
// Columns [Ncols, padz) of Out are written 0 (to establish zero K-padding for the
// following dense GEMM); columns >= padz untouched.
__global__ void __launch_bounds__(256) einsum_kernel(const int* __restrict__ adj,
                              const float* __restrict__ X, int ldx,
                              float* __restrict__ Out, int ldo, int Ncols, int padz)
{
    __shared__ __align__(16) float As[2][8][68];   // [k][m], padded
    __shared__ __align__(16) float Bs[2][8][68];   // [k][n], padded
    const int b  = blockIdx.z;
    const int m0 = blockIdx.y * 64;
    const int n0 = blockIdx.x * 64;
    const int tid = threadIdx.x;
    const int tr = tid >> 4, tc = tid & 15;
    const int* Ab = adj + (size_t)b * (T_ * T_);
    const float* Xb = X + (size_t)b * T_ * ldx;

    float ra[2], rb[2];
    // ---- prologue: load k0 = 0 into buffer 0 ----
    #pragma unroll
    for (int i = 0; i < 2; i++) {
        int slot = tid + i * 256;                // 64m x 8k
        int r = slot >> 3, c = slot & 7;
        ra[i] = (m0 + r < T_) ? (float)Ab[(m0 + r) * T_ + c] : 0.f;
    }
    #pragma unroll
    for (int i = 0; i < 2; i++) {
        int idx = tid + i * 256;                 // 8k x 64n
        int r = idx >> 6, c = idx & 63;
        rb[i] = (n0 + c < Ncols) ? Xb[r * ldx + n0 + c] : 0.f;
    }
    #pragma unroll
    for (int i = 0; i < 2; i++) { int s = tid + i*256; As[0][s & 7][s >> 3] = ra[i]; }
    #pragma unroll
    for (int i = 0; i < 2; i++) { int s = tid + i*256; Bs[0][s >> 6][s & 63] = rb[i]; }
    __syncthreads();

    float acc[4][4] = {};
    const int NSTEP = T_ / 8;                    // 25
    for (int s = 0; s < NSTEP; s++) {
        int p = s & 1;
        if (s + 1 < NSTEP) {
            int k0 = (s + 1) * 8;
            #pragma unroll
            for (int i = 0; i < 2; i++) {
                int slot = tid + i * 256;
                int r = slot >> 3, c = slot & 7;
                ra[i] = (m0 + r < T_) ? (float)Ab[(m0 + r) * T_ + k0 + c] : 0.f;
            }
            #pragma unroll
            for (int i = 0; i < 2; i++) {
                int idx = tid + i * 256;
                int r = idx >> 6, c = idx & 63;
                rb[i] = (n0 + c < Ncols) ? Xb[(k0 + r) * ldx + n0 + c] : 0.f;
            }
        }
        #pragma unroll
        for (int kk = 0; kk < 8; kk++) {
            float4 a  = *reinterpret_cast<const float4*>(&As[p][kk][tr * 4]);
            float4 bv = *reinterpret_cast<const float4*>(&Bs[p][kk][tc * 4]);
            float av[4] = {a.x, a.y, a.z, a.w};
            float bw[4] = {bv.x, bv.y, bv.z, bv.w};
            #pragma unroll
            for (int i = 0; i < 4; i++)
                #pragma unroll
                for (int j = 0; j < 4; j++)
                    acc[i][j] = fmaf(av[i], bw[j], acc[i][j]);
        }
        if (s + 1 < NSTEP) {
            int q = 1 - p;
            #pragma unroll
            for (int i = 0; i < 2; i++) { int t = tid + i*256; As[q][t & 7][t >> 3] = ra[i]; }
            #pragma unroll
            for (int i = 0; i < 2; i++) { int t = tid + i*256; Bs[q][t >> 6][t & 63] = rb[i]; }
            __syncthreads();
        }
    }
    #pragma unroll
    for (int i = 0; i < 4; i++) {
        int m = m0 + tr * 4 + i;
        if (m >= T_) continue;
        #pragma unroll
        for (int j = 0; j < 4; j++) {
            int n = n0 + tc * 4 + j;
            float* o = &Out[((size_t)b * T_ + m) * ldo + n];
            if (n < Ncols)       *o = acc[i][j] + Xb[m * ldx + n];
            else if (n < padz)   *o = 0.f;
        }
    }
}

// ---------------- dense GEMM: C = relu((A@W + 2*bias) * invden) ----------------
// 256x64 tile, BK=16, 256 threads, 8x8/thread, double-buffered.
// M % 256 == 0. A is read guard-free as float4 over [0, 16*nsteps) columns of each
// row (lda >= 16*nsteps, pad columns are zero). W guarded with true K, N.
__global__ void __launch_bounds__(256) dense_gemm_kernel(
        const float* __restrict__ A, int lda, int nsteps,
        const float* __restrict__ W, int K, int N,
        const float* __restrict__ bias, const float* __restrict__ invden,
        float* __restrict__ C, int ldc)
{
    __shared__ __align__(16) float As[2][16][260];   // [k][m], padded
    __shared__ __align__(16) float Bs[2][16][68];    // [k][n], padded
    const int tid = threadIdx.x;
    const int m0 = blockIdx.y * 256;
    const int n0 = blockIdx.x * 64;
    const int tr = tid >> 3, tc = tid & 7;           // 32 x 8 thread grid

    float4 ra[4]; float rb[4];
    // ---- prologue: k0 = 0 into buffer 0 ----
    #pragma unroll
    for (int i = 0; i < 4; i++) {
        int slot = tid + i * 256;                    // 1024 float4 slots = 256m x 16k
        int r = slot >> 2, cq = slot & 3;
        ra[i] = *reinterpret_cast<const float4*>(&A[(size_t)(m0 + r) * lda + cq * 4]);
    }
    #pragma unroll
    for (int i = 0; i < 4; i++) {
        int idx = tid + i * 256;                     // 16k x 64n
        int r = idx >> 6, c = idx & 63;
        rb[i] = (r < K && n0 + c < N) ? W[(size_t)r * N + n0 + c] : 0.f;
    }
    #pragma unroll
    for (int i = 0; i < 4; i++) {
        int slot = tid + i * 256; int r = slot >> 2, cq = slot & 3;
        As[0][cq*4+0][r] = ra[i].x; As[0][cq*4+1][r] = ra[i].y;
        As[0][cq*4+2][r] = ra[i].z; As[0][cq*4+3][r] = ra[i].w;
    }
    #pragma unroll
    for (int i = 0; i < 4; i++) { int t = tid + i*256; Bs[0][t >> 6][t & 63] = rb[i]; }
    __syncthreads();

    float acc[8][8] = {};
    for (int s = 0; s < nsteps; s++) {
        int p = s & 1;
        if (s + 1 < nsteps) {
            int k0 = (s + 1) * 16;
            #pragma unroll
            for (int i = 0; i < 4; i++) {
                int slot = tid + i * 256; int r = slot >> 2, cq = slot & 3;
                ra[i] = *reinterpret_cast<const float4*>(&A[(size_t)(m0 + r) * lda + k0 + cq * 4]);
            }
            #pragma unroll
            for (int i = 0; i < 4; i++) {
                int idx = tid + i * 256; int r = idx >> 6, c = idx & 63;
                int gk = k0 + r;
                rb[i] = (gk < K && n0 + c < N) ? W[(size_t)gk * N + n0 + c] : 0.f;
            }
        }
        #pragma unroll
        for (int kk = 0; kk < 16; kk++) {
            float4 a0 = *reinterpret_cast<const float4*>(&As[p][kk][tr * 8]);
            float4 a1 = *reinterpret_cast<const float4*>(&As[p][kk][tr * 8 + 4]);
            float4 b0 = *reinterpret_cast<const float4*>(&Bs[p][kk][tc * 8]);
            float4 b1 = *reinterpret_cast<const float4*>(&Bs[p][kk][tc * 8 + 4]);
            float av[8] = {a0.x,a0.y,a0.z,a0.w,a1.x,a1.y,a1.z,a1.w};
            float bv[8] = {b0.x,b0.y,b0.z,b0.w,b1.x,b1.y,b1.z,b1.w};
            #pragma unroll
            for (int i = 0; i < 8; i++)
                #pragma unroll
                for (int j = 0; j < 8; j++)
                    acc[i][j] = fmaf(av[i], bv[j], acc[i][j]);
        }
        if (s + 1 < nsteps) {
            int q = 1 - p;
            #pragma unroll
            for (int i = 0; i < 4; i++) {
                int slot = tid + i * 256; int r = slot >> 2, cq = slot & 3;
                As[q][cq*4+0][r] = ra[i].x; As[q][cq*4+1][r] = ra[i].y;
                As[q][cq*4+2][r] = ra[i].z; As[q][cq*4+3][r] = ra[i].w;
            }
            #pragma unroll
            for (int i = 0; i < 4; i++) { int t = tid + i*256; Bs[q][t >> 6][t & 63] = rb[i]; }
            __syncthreads();
        }
    }

    // ---- epilogue: relu((acc + 2b) * invden) ----
    float bn[8];
    #pragma unroll
    for (int j = 0; j < 8; j++) {
        int n = n0 + tc * 8 + j;
        bn[j] = (n < N) ? 2.0f * bias[n] : 0.f;
    }
    const bool full = (n0 + 64 <= N);
    #pragma unroll
    for (int i = 0; i < 8; i++) {
        int m = m0 + tr * 8 + i;
        float inv = invden[m];
        float v[8];
        #pragma unroll
        for (int j = 0; j < 8; j++) v[j] = fmaxf((acc[i][j] + bn[j]) * inv, 0.f);
        float* cp = &C[(size_t)m * ldc + n0 + tc * 8];
        if (full) {
            *reinterpret_cast<float4*>(cp)     = make_float4(v[0], v[1], v[2], v[3]);
            *reinterpret_cast<float4*>(cp + 4) = make_float4(v[4], v[5], v[6], v[7]);
        } else {
            #pragma unroll
            for (int j = 0; j < 8; j++)
                if (n0 + tc * 8 + j < N) cp[j] = v[j];
        }
    }
}

// ---------------- launch ----------------
extern "C" void kernel_launch(void* const* d_in, const int* in_sizes, int n_in,
                              void* d_out, int out_size)
{
    const int* adj      = (const int*)d_in[0];
    const int* words    = (const int*)d_in[1];
    const int* pos      = (const int*)d_in[2];
    const int* ner      = (const int*)d_in[3];
    const int* dep_ids  = (const int*)d_in[4];
    const int* dep_mask = (const int*)d_in[5];
    int base = n_in - 8;                    // trailing 8 arrays are fixed
    const float* word_emb = (const float*)d_in[base + 0];
    const float* pos_emb  = (const float*)d_in[base + 1];
    const float* ner_emb  = (const float*)d_in[base + 2];
    const float* dep_emb  = (const float*)d_in[base + 3];
    const float* W0_w     = (const float*)d_in[base + 4];
    const float* W0_b     = (const float*)d_in[base + 5];
    const float* W1_w     = (const float*)d_in[base + 6];
    const float* W1_b     = (const float*)d_in[base + 7];

    float* out = (float*)d_out;

    void *px, *pS, *ph, *pinv, *pmaskpad;
    cudaGetSymbolAddress(&px, g_x);
    cudaGetSymbolAddress(&pS, g_S);
    cudaGetSymbolAddress(&ph, g_h);
    cudaGetSymbolAddress(&pinv, g_invden);
    cudaGetSymbolAddress(&pmaskpad, g_maskpad);
    float* gx   = (float*)px;
    float* gS   = (float*)pS;
    float* gh   = (float*)ph;
    float* ginv = (float*)pinv;

    float* mask_out = ((long long)out_size >= (long long)BT_ * MEM_ + BT_)
                        ? (out + (size_t)BT_ * MEM_) : (float*)pmaskpad;

    dim3 blk(256);

    // 1) embeddings + dep columns of S1
    prep_kernel<<<BT_ / 8, blk>>>(words, pos, ner, dep_ids, dep_mask,
                                  word_emb, pos_emb, ner_emb, dep_emb);

    // 2) denom + out_mask
    maskden_kernel<<<B_, blk>>>(adj, mask_out);

    // 3) S1[:, :360] = A@x + x            (cols 360..389 = dep from prep; 390..399 zero)
    einsum_kernel<<<dim3(6, 4, B_), blk>>>(adj, gx, IN_DIM, gS, SLD, IN_DIM, IN_DIM);

    // 4) h = relu((S1 @ W0 + 2*b0) * invden)   K=390 padded to 400 (25 steps)
    dense_gemm_kernel<<<dim3(5, BT_ / 256), blk>>>(gS, SLD, 25, W0_w, IN0, MEM_,
                                                   W0_b, ginv, gh, HLD);

    // 5) S2 = A@h + h  (into g_x, stride 304; cols 300..303 zero-filled)
    einsum_kernel<<<dim3(5, 4, B_), blk>>>(adj, gh, HLD, gx, HLD, MEM_, HLD);

    // 6) out = relu((S2 @ W1 + 2*b1) * invden)  K=300 padded to 304 (19 steps)
    dense_gemm_kernel<<<dim3(5, BT_ / 256), blk>>>(gx, HLD, 19, W1_w, MEM_, MEM_,
                                                   W1_b, ginv, out, MEM_);
}

// round 13
// speedup vs baseline: 1.2184x; 1.2106x over previous
#include <cuda_runtime.h>
#include <cuda_bf16.h>
#include <cstdint>
#include <cstddef>

// ---------------- problem constants ----------------
#define B_     256
#define T_     200
#define KDEP   5
#define EMB_   300
#define SMALLD 30
#define IN_DIM 360      // 300 + 30 + 30
#define IN0    390      // 360 + 30 (true K of GEMM0)
#define MEM_   300
#define BT_    (B_*T_)  // 51200
#define SLD    400      // S1 row stride (390 valid, pads zero) = GEMM0 padded K (25*16)
#define HLD    304      // h / S2 row stride (300 valid, pads zero) = GEMM1 padded K (19*16)

// ---------------- static device scratch (zero-initialized, never freed) ----------------
__device__ __align__(16) float g_x[(size_t)BT_*IN_DIM + 64]; // x [BT,360]; reused as S2 [BT,304]
__device__ __align__(16) float g_S[(size_t)BT_*SLD   + 64];  // S1 [BT,400]; cols 390..399 stay 0
__device__ __align__(16) float g_h[(size_t)BT_*HLD   + 64];  // h  [BT,304]; cols 300..303 stay 0
__device__ float g_invden[BT_];
__device__ float g_maskpad[BT_];

// ---------------- packed f32x2 helpers (Blackwell FFMA2 path) ----------------
__device__ __forceinline__ void ffma2(unsigned long long& d,
                                      unsigned long long a, unsigned long long b) {
    asm("fma.rn.f32x2 %0, %1, %2, %0;" : "+l"(d) : "l"(a), "l"(b));
}
__device__ __forceinline__ unsigned long long dup2(float v) {
    unsigned long long d;
    asm("mov.b64 %0, {%1, %1};" : "=l"(d) : "r"(__float_as_uint(v)));
    return d;
}
__device__ __forceinline__ float2 unpack2(unsigned long long v) {
    float2 f;
    asm("mov.b64 {%0, %1}, %2;" : "=f"(f.x), "=f"(f.y) : "l"(v));
    return f;
}

// ---------------- prep: embedding gathers + dep ragged sum ----------------
__global__ void prep_kernel(const int* __restrict__ words, const int* __restrict__ pos,
                            const int* __restrict__ ner, const int* __restrict__ dep_ids,
                            const int* __restrict__ dep_mask,
                            const float* __restrict__ word_emb, const float* __restrict__ pos_emb,
                            const float* __restrict__ ner_emb, const float* __restrict__ dep_emb)
{
    int warp = threadIdx.x >> 5, lane = threadIdx.x & 31;
    int i = blockIdx.x * 8 + warp;            // token index
    if (i >= BT_) return;

    const float* wrow = word_emb + (size_t)words[i] * EMB_;
    float* xrow = g_x + (size_t)i * IN_DIM;
    #pragma unroll
    for (int j = lane; j < EMB_; j += 32) xrow[j] = wrow[j];

    if (lane < SMALLD) {
        xrow[300 + lane] = pos_emb[pos[i] * SMALLD + lane];
        xrow[330 + lane] = ner_emb[ner[i] * SMALLD + lane];
        float s = 0.f; int cnt = 0;
        #pragma unroll
        for (int k = 0; k < KDEP; k++) {
            int m = dep_mask[i * KDEP + k];
            cnt += m;
            if (m) s += dep_emb[dep_ids[i * KDEP + k] * SMALLD + lane];
        }
        if (cnt == 0) s = dep_emb[lane];          // dep_emb[0]
        s += dep_emb[SMALLD + lane];              // + dep_emb[SELF_LOOP_ID=1]
        g_S[(size_t)i * SLD + IN_DIM + lane] = s; // cols 360..389
    }
}

// ---------------- denom (1/(rowsum+1)) + out_mask ----------------
__global__ void maskden_kernel(const int* __restrict__ adj, float* __restrict__ mask_out)
{
    __shared__ float rs_sh[T_];
    int b = blockIdx.x;
    int tid = threadIdx.x;                     // 256
    const int* Ab = adj + (size_t)b * T_ * T_;

    int col = 0;
    if (tid < T_) {
        for (int s = 0; s < T_; s++) col += Ab[s * T_ + tid];
    }
    int warp = tid >> 5, lane = tid & 31;
    for (int row = warp; row < T_; row += 8) {
        int acc = 0;
        for (int j = lane; j < T_; j += 32) acc += Ab[row * T_ + j];
        #pragma unroll
        for (int off = 16; off; off >>= 1) acc += __shfl_down_sync(0xffffffffu, acc, off);
        if (lane == 0) rs_sh[row] = (float)acc;
    }
    __syncthreads();
    if (tid < T_) {
        float rs = rs_sh[tid];
        g_invden[b * T_ + tid] = 1.0f / (rs + 1.0f);
        mask_out[b * T_ + tid] = ((rs + (float)col) == 0.0f) ? 1.0f : 0.0f;
    }
}

// ---------------- batched einsum: Out[b] = adj[b] @ X[b] + X[b] ----------------
// 64x64 tile, BK=8, 256 threads, 4x4/thread via m-paired f32x2, double-buffered.
// Writes zeros into columns [Ncols, padz) of Out (K-padding for the next GEMM).
__global__ void __launch_bounds__(256) einsum_kernel(const int* __restrict__ adj,
                              const float* __restrict__ X, int ldx,
                              float* __restrict__ Out, int ldo, int Ncols, int padz)
{
    __shared__ __align__(16) float As[2][8][68];   // [k][m] (m contiguous), padded
    __shared__ __align__(16) float Bs[2][8][68];   // [k][n], padded
    const int b  = blockIdx.z;
    const int m0 = blockIdx.y * 64;
    const int n0 = blockIdx.x * 64;
    const int tid = threadIdx.x;
    const int tr = tid >> 4, tc = tid & 15;
    const int* Ab = adj + (size_t)b * (T_ * T_);
    const float* Xb = X + (size_t)b * T_ * ldx;

    float ra[2], rb[2];
    // ---- prologue: k0 = 0 into buffer 0 ----
    #pragma unroll
    for (int i = 0; i < 2; i++) {
        int slot = tid + i * 256;                // 64m x 8k
        int r = slot >> 3, c = slot & 7;
        ra[i] = (m0 + r < T_) ? (float)Ab[(m0 + r) * T_ + c] : 0.f;
    }
    #pragma unroll
    for (int i = 0; i < 2; i++) {
        int idx = tid + i * 256;                 // 8k x 64n
        int r = idx >> 6, c = idx & 63;
        rb[i] = (n0 + c < Ncols) ? Xb[r * ldx + n0 + c] : 0.f;
    }
    #pragma unroll
    for (int i = 0; i < 2; i++) { int s = tid + i*256; As[0][s & 7][s >> 3] = ra[i]; }
    #pragma unroll
    for (int i = 0; i < 2; i++) { int s = tid + i*256; Bs[0][s >> 6][s & 63] = rb[i]; }
    __syncthreads();

    unsigned long long accp[2][4] = {};          // m-pairs x 4 n
    const int NSTEP = T_ / 8;                    // 25
    for (int s = 0; s < NSTEP; s++) {
        int p = s & 1;
        if (s + 1 < NSTEP) {
            int k0 = (s + 1) * 8;
            #pragma unroll
            for (int i = 0; i < 2; i++) {
                int slot = tid + i * 256;
                int r = slot >> 3, c = slot & 7;
                ra[i] = (m0 + r < T_) ? (float)Ab[(m0 + r) * T_ + k0 + c] : 0.f;
            }
            #pragma unroll
            for (int i = 0; i < 2; i++) {
                int idx = tid + i * 256;
                int r = idx >> 6, c = idx & 63;
                rb[i] = (n0 + c < Ncols) ? Xb[(k0 + r) * ldx + n0 + c] : 0.f;
            }
        }
        #pragma unroll
        for (int kk = 0; kk < 8; kk++) {
            ulonglong2 ap = *reinterpret_cast<const ulonglong2*>(&As[p][kk][tr * 4]);
            float4 bv = *reinterpret_cast<const float4*>(&Bs[p][kk][tc * 4]);
            unsigned long long bd[4] = { dup2(bv.x), dup2(bv.y), dup2(bv.z), dup2(bv.w) };
            #pragma unroll
            for (int j = 0; j < 4; j++) { ffma2(accp[0][j], ap.x, bd[j]); }
            #pragma unroll
            for (int j = 0; j < 4; j++) { ffma2(accp[1][j], ap.y, bd[j]); }
        }
        if (s + 1 < NSTEP) {
            int q = 1 - p;
            #pragma unroll
            for (int i = 0; i < 2; i++) { int t = tid + i*256; As[q][t & 7][t >> 3] = ra[i]; }
            #pragma unroll
            for (int i = 0; i < 2; i++) { int t = tid + i*256; Bs[q][t >> 6][t & 63] = rb[i]; }
            __syncthreads();
        }
    }
    #pragma unroll
    for (int mi = 0; mi < 2; mi++) {
        #pragma unroll
        for (int half = 0; half < 2; half++) {
            int m = m0 + tr * 4 + 2 * mi + half;
            if (m >= T_) continue;
            #pragma unroll
            for (int j = 0; j < 4; j++) {
                float2 v = unpack2(accp[mi][j]);
                float a = half ? v.y : v.x;
                int n = n0 + tc * 4 + j;
                float* o = &Out[((size_t)b * T_ + m) * ldo + n];
                if (n < Ncols)     *o = a + Xb[m * ldx + n];
                else if (n < padz) *o = 0.f;
            }
        }
    }
}

// ---------------- dense GEMM: C = relu((A@W + 2*bias) * invden) ----------------
// 128x64 tile, BK=16, 256 threads, 8x4/thread via m-paired f32x2, double-buffered.
// M % 128 == 0. A read guard-free as float4 (lda >= 16*nsteps, pad cols zero).
__global__ void __launch_bounds__(256) dense_gemm_kernel(
        const float* __restrict__ A, int lda, int nsteps,
        const float* __restrict__ W, int K, int N,
        const float* __restrict__ bias, const float* __restrict__ invden,
        float* __restrict__ C, int ldc)
{
    __shared__ __align__(16) float As[2][16][132];   // [k][m] (m contiguous), padded
    __shared__ __align__(16) float Bs[2][16][68];    // [k][n], padded
    const int tid = threadIdx.x;
    const int m0 = blockIdx.y * 128;
    const int n0 = blockIdx.x * 64;
    const int tr = tid >> 4, tc = tid & 15;          // 16 x 16 thread grid

    float4 ra[2]; float rb[4];
    // ---- prologue: k0 = 0 into buffer 0 ----
    #pragma unroll
    for (int i = 0; i < 2; i++) {
        int slot = tid + i * 256;                    // 512 float4 slots = 128m x 4 quads
        int r = slot >> 2, cq = slot & 3;
        ra[i] = *reinterpret_cast<const float4*>(&A[(size_t)(m0 + r) * lda + cq * 4]);
    }
    #pragma unroll
    for (int i = 0; i < 4; i++) {
        int idx = tid + i * 256;                     // 16k x 64n
        int r = idx >> 6, c = idx & 63;
        rb[i] = (r < K && n0 + c < N) ? W[(size_t)r * N + n0 + c] : 0.f;
    }
    #pragma unroll
    for (int i = 0; i < 2; i++) {
        int slot = tid + i * 256; int r = slot >> 2, cq = slot & 3;
        As[0][cq*4+0][r] = ra[i].x; As[0][cq*4+1][r] = ra[i].y;
        As[0][cq*4+2][r] = ra[i].z; As[0][cq*4+3][r] = ra[i].w;
    }
    #pragma unroll
    for (int i = 0; i < 4; i++) { int t = tid + i*256; Bs[0][t >> 6][t & 63] = rb[i]; }
    __syncthreads();

    unsigned long long accp[4][4] = {};              // 4 m-pairs x 4 n
    for (int s = 0; s < nsteps; s++) {
        int p = s & 1;
        if (s + 1 < nsteps) {
            int k0 = (s + 1) * 16;
            #pragma unroll
            for (int i = 0; i < 2; i++) {
                int slot = tid + i * 256; int r = slot >> 2, cq = slot & 3;
                ra[i] = *reinterpret_cast<const float4*>(&A[(size_t)(m0 + r) * lda + k0 + cq * 4]);
            }
            #pragma unroll
            for (int i = 0; i < 4; i++) {
                int idx = tid + i * 256; int r = idx >> 6, c = idx & 63;
                int gk = k0 + r;
                rb[i] = (gk < K && n0 + c < N) ? W[(size_t)gk * N + n0 + c] : 0.f;
            }
        }
        #pragma unroll
        for (int kk = 0; kk < 16; kk++) {
            ulonglong2 a01 = *reinterpret_cast<const ulonglong2*>(&As[p][kk][tr * 8]);
            ulonglong2 a23 = *reinterpret_cast<const ulonglong2*>(&As[p][kk][tr * 8 + 4]);
            float4 bv = *reinterpret_cast<const float4*>(&Bs[p][kk][tc * 4]);
            unsigned long long bd[4] = { dup2(bv.x), dup2(bv.y), dup2(bv.z), dup2(bv.w) };
            #pragma unroll
            for (int j = 0; j < 4; j++) { ffma2(accp[0][j], a01.x, bd[j]); }
            #pragma unroll
            for (int j = 0; j < 4; j++) { ffma2(accp[1][j], a01.y, bd[j]); }
            #pragma unroll
            for (int j = 0; j < 4; j++) { ffma2(accp[2][j], a23.x, bd[j]); }
            #pragma unroll
            for (int j = 0; j < 4; j++) { ffma2(accp[3][j], a23.y, bd[j]); }
        }
        if (s + 1 < nsteps) {
            int q = 1 - p;
            #pragma unroll
            for (int i = 0; i < 2; i++) {
                int slot = tid + i * 256; int r = slot >> 2, cq = slot & 3;
                As[q][cq*4+0][r] = ra[i].x; As[q][cq*4+1][r] = ra[i].y;
                As[q][cq*4+2][r] = ra[i].z; As[q][cq*4+3][r] = ra[i].w;
            }
            #pragma unroll
            for (int i = 0; i < 4; i++) { int t = tid + i*256; Bs[q][t >> 6][t & 63] = rb[i]; }
            __syncthreads();
        }
    }

    // ---- epilogue: relu((acc + 2b) * invden) ----
    float bn[4];
    #pragma unroll
    for (int j = 0; j < 4; j++) {
        int n = n0 + tc * 4 + j;
        bn[j] = (n < N) ? 2.0f * bias[n] : 0.f;
    }
    #pragma unroll
    for (int mi = 0; mi < 4; mi++) {
        int me = m0 + tr * 8 + 2 * mi;
        float inv_e = invden[me], inv_o = invden[me + 1];
        float ve[4], vo[4];
        #pragma unroll
        for (int j = 0; j < 4; j++) {
            float2 v = unpack2(accp[mi][j]);
            ve[j] = fmaxf((v.x + bn[j]) * inv_e, 0.f);
            vo[j] = fmaxf((v.y + bn[j]) * inv_o, 0.f);
        }
        float* ce = &C[(size_t)me * ldc + n0 + tc * 4];
        float* co = &C[(size_t)(me + 1) * ldc + n0 + tc * 4];
        if (n0 + tc * 4 + 4 <= N) {
            *reinterpret_cast<float4*>(ce) = make_float4(ve[0], ve[1], ve[2], ve[3]);
            *reinterpret_cast<float4*>(co) = make_float4(vo[0], vo[1], vo[2], vo[3]);
        } else {
            #pragma unroll
            for (int j = 0; j < 4; j++) {
                if (n0 + tc * 4 + j < N) { ce[j] = ve[j]; co[j] = vo[j]; }
            }
        }
    }
}

// ---------------- launch ----------------
extern "C" void kernel_launch(void* const* d_in, const int* in_sizes, int n_in,
                              void* d_out, int out_size)
{
    const int* adj      = (const int*)d_in[0];
    const int* words    = (const int*)d_in[1];
    const int* pos      = (const int*)d_in[2];
    const int* ner      = (const int*)d_in[3];
    const int* dep_ids  = (const int*)d_in[4];
    const int* dep_mask = (const int*)d_in[5];
    int base = n_in - 8;                    // trailing 8 arrays are fixed
    const float* word_emb = (const float*)d_in[base + 0];
    const float* pos_emb  = (const float*)d_in[base + 1];
    const float* ner_emb  = (const float*)d_in[base + 2];
    const float* dep_emb  = (const float*)d_in[base + 3];
    const float* W0_w     = (const float*)d_in[base + 4];
    const float* W0_b     = (const float*)d_in[base + 5];
    const float* W1_w     = (const float*)d_in[base + 6];
    const float* W1_b     = (const float*)d_in[base + 7];

    float* out = (float*)d_out;

    void *px, *pS, *ph, *pinv, *pmaskpad;
    cudaGetSymbolAddress(&px, g_x);
    cudaGetSymbolAddress(&pS, g_S);
    cudaGetSymbolAddress(&ph, g_h);
    cudaGetSymbolAddress(&pinv, g_invden);
    cudaGetSymbolAddress(&pmaskpad, g_maskpad);
    float* gx   = (float*)px;
    float* gS   = (float*)pS;
    float* gh   = (float*)ph;
    float* ginv = (float*)pinv;

    float* mask_out = ((long long)out_size >= (long long)BT_ * MEM_ + BT_)
                        ? (out + (size_t)BT_ * MEM_) : (float*)pmaskpad;

    dim3 blk(256);

    // 1) embeddings + dep columns of S1
    prep_kernel<<<BT_ / 8, blk>>>(words, pos, ner, dep_ids, dep_mask,
                                  word_emb, pos_emb, ner_emb, dep_emb);

    // 2) denom + out_mask
    maskden_kernel<<<B_, blk>>>(adj, mask_out);

    // 3) S1[:, :360] = A@x + x   (cols 360..389 from prep; 390..399 static zero)
    einsum_kernel<<<dim3(6, 4, B_), blk>>>(adj, gx, IN_DIM, gS, SLD, IN_DIM, IN_DIM);

    // 4) h = relu((S1 @ W0 + 2*b0) * invden)   K=390 padded to 400 (25 steps)
    dense_gemm_kernel<<<dim3(5, BT_ / 128), blk>>>(gS, SLD, 25, W0_w, IN0, MEM_,
                                                   W0_b, ginv, gh, HLD);

    // 5) S2 = A@h + h  (into g_x, stride 304; cols 300..303 zero-filled)
    einsum_kernel<<<dim3(5, 4, B_), blk>>>(adj, gh, HLD, gx, HLD, MEM_, HLD);

    // 6) out = relu((S2 @ W1 + 2*b1) * invden)  K=300 padded to 304 (19 steps)
    dense_gemm_kernel<<<dim3(5, BT_ / 128), blk>>>(gx, HLD, 19, W1_w, MEM_, MEM_,
                                                   W1_b, ginv, out, MEM_);
}